// round 6
// baseline (speedup 1.0000x reference)
#include <cuda_runtime.h>
#include <cuda_bf16.h>
#include <math.h>
#include <stdint.h>

// ----------------------------------------------------------------------------
// Problem constants (this instance): M=D=10000, FG=FD=256, H1=2, K=64, E=320000
// ----------------------------------------------------------------------------
#define MAXN 10000
#define MAXE 320000
#define CDIM 256

// ------------------------- device scratch (no mallocs) ----------------------
__device__ float g_bufA[MAXN * 512];
__device__ float g_bufB[MAXN * 512];
__device__ float g_bufC[MAXN * 256];
__device__ float g_als[MAXN * 2];
__device__ float g_ald[MAXN * 2];
__device__ float g_elog[MAXE * 2];
__device__ int   g_deg[MAXN + 1];
__device__ int   g_off[MAXN + 1];
__device__ int   g_cur[MAXN];
__device__ int   g_sorted[MAXE];
__device__ float g_xfin[MAXN * 64];
__device__ float g2_bufA[MAXN * 512];
__device__ float g2_bufB[MAXN * 512];
__device__ float g2_bufC[MAXN * 256];
__device__ float g2_als[MAXN * 2];
__device__ float g2_ald[MAXN * 2];
__device__ float g2_elog[MAXE * 2];
__device__ int   g2_deg[MAXN + 1];
__device__ int   g2_off[MAXN + 1];
__device__ int   g2_cur[MAXN];
__device__ int   g2_sorted[MAXE];
__device__ float g_yfin[MAXN * 64];

// ------------------------------ tiny kernels --------------------------------
__global__ void zero_int_kernel(int* p, int n) {
    int i = blockIdx.x * blockDim.x + threadIdx.x;
    if (i < n) p[i] = 0;
}

__global__ void hist_kernel(const int* __restrict__ dst, int E, int* __restrict__ deg) {
    int e = blockIdx.x * blockDim.x + threadIdx.x;
    if (e < E) atomicAdd(&deg[dst[e]], 1);
}

__global__ void scan_kernel(const int* __restrict__ deg, int* __restrict__ off, int n) {
    const int T = 1024;
    int t = threadIdx.x;
    int chunk = (n + T - 1) / T;
    int b = t * chunk;
    int e2 = b + chunk; if (e2 > n) e2 = n;
    int s = 0;
    for (int i = b; i < e2; i++) s += deg[i];
    __shared__ int sh[T];
    sh[t] = s;
    __syncthreads();
    for (int d2 = 1; d2 < T; d2 <<= 1) {
        int v = (t >= d2) ? sh[t - d2] : 0;
        __syncthreads();
        sh[t] += v;
        __syncthreads();
    }
    int run = (t == 0) ? 0 : sh[t - 1];
    for (int i = b; i < e2; i++) { off[i] = run; run += deg[i]; }
    if (t == 0) off[n] = sh[T - 1];
}

__global__ void scatter_kernel(const int* __restrict__ dst, int E,
                               const int* __restrict__ off, int* __restrict__ cur,
                               int* __restrict__ sorted) {
    int e = blockIdx.x * blockDim.x + threadIdx.x;
    if (e < E) {
        int d = dst[e];
        int p = atomicAdd(&cur[d], 1);
        sorted[off[d] + p] = e;
    }
}

// ------------------------ tf32x3 GEMM via mma.sync --------------------------
// C[M,N] = A[M,K] @ op(B) (+bias, +relu). bRowMajor=0 -> B is BT [N,K];
// bRowMajor=1 -> B is [K,N]. Fragment-major SMEM: one float4
// {hi(k),hi(k+4),lo(k),lo(k+4)} per (row, kstep, kq); row stride 12 float4s +
// XOR swizzle (kq ^ (r&3)) -> conflict-free STS.128 and LDS.128.
#define BM 128
#define BN 128
#define ROWF4 12   // float4 stride per row (== 4 mod 8)

__device__ __forceinline__ float tf32_rn(float a) {
    uint32_t u;
    asm("cvt.rna.tf32.f32 %0, %1;" : "=r"(u) : "f"(a));
    return __uint_as_float(u);
}

__device__ __forceinline__ void mma_m16n8k8(float* c, const uint32_t* a,
                                            const uint32_t* b) {
    asm volatile(
        "mma.sync.aligned.m16n8k8.row.col.f32.tf32.tf32.f32 "
        "{%0,%1,%2,%3}, {%4,%5,%6,%7}, {%8,%9}, {%0,%1,%2,%3};"
        : "+f"(c[0]), "+f"(c[1]), "+f"(c[2]), "+f"(c[3])
        : "r"(a[0]), "r"(a[1]), "r"(a[2]), "r"(a[3]), "r"(b[0]), "r"(b[1]));
}

__device__ __forceinline__ int frag_idx(int r, int s, int kq) {
    return r * ROWF4 + s * 4 + (kq ^ (r & 3));
}

__global__ __launch_bounds__(256)
void mma_gemm_kernel(int M, int N, int K,
                     const float* __restrict__ A,
                     const float* __restrict__ B,
                     int bRowMajor,
                     const float* __restrict__ bias,
                     float* __restrict__ C, int doRelu) {
    __shared__ float4 AsP[BM * ROWF4];   // 24 KB
    __shared__ float4 BsP[BN * ROWF4];   // 24 KB

    int tid = threadIdx.x, lane = tid & 31, wid = tid >> 5;
    int mBase = blockIdx.y * BM, nBase = blockIdx.x * BN;
    int wm = (wid & 3) * 32;
    int wn = (wid >> 2) * 64;

    float acc[2][8][4];
#pragma unroll
    for (int i = 0; i < 2; i++)
#pragma unroll
        for (int j = 0; j < 8; j++)
#pragma unroll
            for (int l = 0; l < 4; l++) acc[i][j][l] = 0.f;

    // column-major loader mapping: 1 item/thread = row r, kstep s, 8 floats
    int cRow = tid >> 1, cS = tid & 1;
    // row-major B loader mapping: 2 items/thread, each float4 along n
    int bKk[2], bN4[2];
#pragma unroll
    for (int it = 0; it < 2; it++) {
        int idx = tid + it * 256;
        bKk[it] = idx >> 5;            // k within chunk (0..15)
        bN4[it] = (idx & 31) * 4;      // n quad base
    }

    int KC = K >> 4;
    float4 pa0, pa1, pb0, pb1;   // prefetch regs (col-major: two float4 per op)
    float4 pbr[2];               // row-major B prefetch

    auto loadA = [&](int k0) {
        int gm = mBase + cRow;
        if (gm < M) {
            const float* p = &A[(size_t)gm * K + k0 + cS * 8];
            pa0 = *(const float4*)p;
            pa1 = *(const float4*)(p + 4);
        } else {
            pa0 = pa1 = make_float4(0.f, 0.f, 0.f, 0.f);
        }
    };
    auto loadB = [&](int k0) {
        if (bRowMajor) {
#pragma unroll
            for (int it = 0; it < 2; it++) {
                int gn = nBase + bN4[it];
                pbr[it] = (gn < N)
                    ? *(const float4*)&B[(size_t)(k0 + bKk[it]) * N + gn]
                    : make_float4(0.f, 0.f, 0.f, 0.f);
            }
        } else {
            int gn = nBase + cRow;
            if (gn < N) {
                const float* p = &B[(size_t)gn * K + k0 + cS * 8];
                pb0 = *(const float4*)p;
                pb1 = *(const float4*)(p + 4);
            } else {
                pb0 = pb1 = make_float4(0.f, 0.f, 0.f, 0.f);
            }
        }
    };
    // assemble 8 consecutive-k floats into 4 fragment float4s and store
    auto storeFrag8 = [&](float4* S, int r, int s, float4 v0, float4 v1) {
        float h0[4] = {tf32_rn(v0.x), tf32_rn(v0.y), tf32_rn(v0.z), tf32_rn(v0.w)};
        float h1[4] = {tf32_rn(v1.x), tf32_rn(v1.y), tf32_rn(v1.z), tf32_rn(v1.w)};
        float l0[4] = {v0.x - h0[0], v0.y - h0[1], v0.z - h0[2], v0.w - h0[3]};
        float l1[4] = {v1.x - h1[0], v1.y - h1[1], v1.z - h1[2], v1.w - h1[3]};
#pragma unroll
        for (int kq = 0; kq < 4; kq++) {
            l0[kq] = tf32_rn(l0[kq]);
            l1[kq] = tf32_rn(l1[kq]);
            S[frag_idx(r, s, kq)] = make_float4(h0[kq], h1[kq], l0[kq], l1[kq]);
        }
    };
    auto storeA = [&]() { storeFrag8(AsP, cRow, cS, pa0, pa1); };
    auto storeB = [&]() {
        if (bRowMajor) {
#pragma unroll
            for (int it = 0; it < 2; it++) {
                int k = bKk[it];
                int s = k >> 3, khl = (k & 7) >> 2, kq = k & 3;
                float* Sf = (float*)BsP;
                float4 v = pbr[it];
                float hv[4] = {tf32_rn(v.x), tf32_rn(v.y), tf32_rn(v.z), tf32_rn(v.w)};
                float lv[4] = {tf32_rn(v.x - hv[0]), tf32_rn(v.y - hv[1]),
                               tf32_rn(v.z - hv[2]), tf32_rn(v.w - hv[3])};
#pragma unroll
                for (int j = 0; j < 4; j++) {
                    int n = bN4[it] + j;
                    int fi = frag_idx(n, s, kq) * 4;
                    Sf[fi + khl] = hv[j];
                    Sf[fi + 2 + khl] = lv[j];
                }
            }
        } else {
            storeFrag8(BsP, cRow, cS, pb0, pb1);
        }
    };

    loadA(0); loadB(0);
    storeA(); storeB();
    __syncthreads();

    for (int ch = 0; ch < KC; ch++) {
        if (ch + 1 < KC) { loadA((ch + 1) << 4); loadB((ch + 1) << 4); }

#pragma unroll
        for (int s = 0; s < 2; s++) {
            int kq = lane & 3;
            uint32_t ah[2][4], al[2][4];
#pragma unroll
            for (int mt = 0; mt < 2; mt++) {
                int r = wm + (lane >> 2) + mt * 16;
                float4 f0 = AsP[frag_idx(r, s, kq)];
                float4 f1 = AsP[frag_idx(r + 8, s, kq)];
                ah[mt][0] = __float_as_uint(f0.x);
                ah[mt][1] = __float_as_uint(f1.x);
                ah[mt][2] = __float_as_uint(f0.y);
                ah[mt][3] = __float_as_uint(f1.y);
                al[mt][0] = __float_as_uint(f0.z);
                al[mt][1] = __float_as_uint(f1.z);
                al[mt][2] = __float_as_uint(f0.w);
                al[mt][3] = __float_as_uint(f1.w);
            }
            uint32_t bh[8][2], bl[8][2];
#pragma unroll
            for (int nt = 0; nt < 8; nt++) {
                int bn = wn + nt * 8 + (lane >> 2);
                float4 g = BsP[frag_idx(bn, s, kq)];
                bh[nt][0] = __float_as_uint(g.x);
                bh[nt][1] = __float_as_uint(g.y);
                bl[nt][0] = __float_as_uint(g.z);
                bl[nt][1] = __float_as_uint(g.w);
            }
            // term-major issue: 16 independent MMAs between acc reuses
#pragma unroll
            for (int nt = 0; nt < 8; nt++)
#pragma unroll
                for (int mt = 0; mt < 2; mt++)
                    mma_m16n8k8(acc[mt][nt], ah[mt], bh[nt]);
#pragma unroll
            for (int nt = 0; nt < 8; nt++)
#pragma unroll
                for (int mt = 0; mt < 2; mt++)
                    mma_m16n8k8(acc[mt][nt], al[mt], bh[nt]);
#pragma unroll
            for (int nt = 0; nt < 8; nt++)
#pragma unroll
                for (int mt = 0; mt < 2; mt++)
                    mma_m16n8k8(acc[mt][nt], ah[mt], bl[nt]);
        }
        __syncthreads();

        if (ch + 1 < KC) {
            storeA(); storeB();
            __syncthreads();
        }
    }

    // epilogue
#pragma unroll
    for (int mt = 0; mt < 2; mt++) {
        int r0 = mBase + wm + mt * 16 + (lane >> 2);
        int r1 = r0 + 8;
#pragma unroll
        for (int nt = 0; nt < 8; nt++) {
            int c = nBase + wn + nt * 8 + (lane & 3) * 2;
            if (c >= N) continue;
            float b0 = bias ? bias[c] : 0.f;
            float b1 = bias ? bias[c + 1] : 0.f;
            if (r0 < M) {
                float v0 = acc[mt][nt][0] + b0;
                float v1 = acc[mt][nt][1] + b1;
                if (doRelu) { v0 = fmaxf(v0, 0.f); v1 = fmaxf(v1, 0.f); }
                *(float2*)&C[(size_t)r0 * N + c] = make_float2(v0, v1);
            }
            if (r1 < M) {
                float v2 = acc[mt][nt][2] + b0;
                float v3 = acc[mt][nt][3] + b1;
                if (doRelu) { v2 = fmaxf(v2, 0.f); v3 = fmaxf(v3, 0.f); }
                *(float2*)&C[(size_t)r1 * N + c] = make_float2(v2, v3);
            }
        }
    }
}

// --------------------------- GAT-specific kernels ---------------------------
__global__ void compute_al(const float* __restrict__ xp,
                           const float* __restrict__ asrc, const float* __restrict__ adst,
                           float* __restrict__ als, float* __restrict__ ald, int H) {
    int n = blockIdx.x, tid = threadIdx.x;
    int HC = H * CDIM;
    __shared__ float sh1[8], sh2[8];
    for (int h = 0; h < H; h++) {
        float v = xp[(size_t)n * HC + h * CDIM + tid];
        float s1 = v * asrc[h * CDIM + tid];
        float s2 = v * adst[h * CDIM + tid];
#pragma unroll
        for (int o = 16; o > 0; o >>= 1) {
            s1 += __shfl_down_sync(0xffffffffu, s1, o);
            s2 += __shfl_down_sync(0xffffffffu, s2, o);
        }
        if ((tid & 31) == 0) { sh1[tid >> 5] = s1; sh2[tid >> 5] = s2; }
        __syncthreads();
        if (tid < 8) {
            s1 = sh1[tid]; s2 = sh2[tid];
#pragma unroll
            for (int o = 4; o > 0; o >>= 1) {
                s1 += __shfl_down_sync(0xffu, s1, o);
                s2 += __shfl_down_sync(0xffu, s2, o);
            }
            if (tid == 0) { als[n * H + h] = s1; ald[n * H + h] = s2; }
        }
        __syncthreads();
    }
}

__global__ void edge_logits(const int* __restrict__ src, const int* __restrict__ dst,
                            const float* __restrict__ als, const float* __restrict__ ald,
                            float* __restrict__ elog, int E, int H) {
    int e = blockIdx.x * blockDim.x + threadIdx.x;
    if (e >= E) return;
    int s = src[e], d = dst[e];
    for (int h = 0; h < H; h++) {
        float v = als[s * H + h] + ald[d * H + h];
        elog[(size_t)e * H + h] = v > 0.f ? v : 0.2f * v;
    }
}

__global__ void gat_aggregate(const float* __restrict__ xp, const float* __restrict__ elog,
                              const int* __restrict__ src, const int* __restrict__ sorted,
                              const int* __restrict__ off, const float* __restrict__ bias,
                              float* __restrict__ out, int H) {
    int d = blockIdx.x, tid = threadIdx.x;
    int beg = off[d];
    int deg = off[d + 1] - beg;
    int HC = H * CDIM;
    __shared__ float sh[8];
    __shared__ float s_bcast;
    __shared__ float s_alpha[256];
    __shared__ int   s_row[256];

    if (deg <= 256) {
        if (tid < deg) s_row[tid] = src[sorted[beg + tid]];
        for (int h = 0; h < H; h++) {
            float mx = -1e30f;
            if (tid < deg) mx = elog[(size_t)sorted[beg + tid] * H + h];
#pragma unroll
            for (int o = 16; o > 0; o >>= 1)
                mx = fmaxf(mx, __shfl_down_sync(0xffffffffu, mx, o));
            if ((tid & 31) == 0) sh[tid >> 5] = mx;
            __syncthreads();
            if (tid < 8) {
                mx = sh[tid];
#pragma unroll
                for (int o = 4; o > 0; o >>= 1)
                    mx = fmaxf(mx, __shfl_down_sync(0xffu, mx, o));
                if (tid == 0) s_bcast = mx;
            }
            __syncthreads();
            float gmax = s_bcast;

            float ee = 0.f;
            if (tid < deg)
                ee = __expf(elog[(size_t)sorted[beg + tid] * H + h] - gmax);
            s_alpha[tid] = ee;
            float sm = ee;
#pragma unroll
            for (int o = 16; o > 0; o >>= 1) sm += __shfl_down_sync(0xffffffffu, sm, o);
            if ((tid & 31) == 0) sh[tid >> 5] = sm;
            __syncthreads();
            if (tid < 8) {
                sm = sh[tid];
#pragma unroll
                for (int o = 4; o > 0; o >>= 1) sm += __shfl_down_sync(0xffu, sm, o);
                if (tid == 0) s_bcast = sm;
            }
            __syncthreads();
            float inv = 1.f / (s_bcast + 1e-16f);

            const float* xph = xp + h * CDIM + tid;
            float a0 = 0.f, a1 = 0.f, a2 = 0.f, a3 = 0.f;
            int j = 0;
            for (; j + 4 <= deg; j += 4) {
                a0 += s_alpha[j + 0] * xph[(size_t)s_row[j + 0] * HC];
                a1 += s_alpha[j + 1] * xph[(size_t)s_row[j + 1] * HC];
                a2 += s_alpha[j + 2] * xph[(size_t)s_row[j + 2] * HC];
                a3 += s_alpha[j + 3] * xph[(size_t)s_row[j + 3] * HC];
            }
            for (; j < deg; j++)
                a0 += s_alpha[j] * xph[(size_t)s_row[j] * HC];
            float acc = ((a0 + a1) + (a2 + a3)) * inv;
            out[(size_t)d * HC + h * CDIM + tid] =
                fmaxf(acc + bias[h * CDIM + tid], 0.f);
            __syncthreads();
        }
        return;
    }

    for (int h = 0; h < H; h++) {
        float mx = -1e30f;
        for (int i = tid; i < deg; i += 256) {
            int e = sorted[beg + i];
            mx = fmaxf(mx, elog[(size_t)e * H + h]);
        }
#pragma unroll
        for (int o = 16; o > 0; o >>= 1) mx = fmaxf(mx, __shfl_down_sync(0xffffffffu, mx, o));
        if ((tid & 31) == 0) sh[tid >> 5] = mx;
        __syncthreads();
        if (tid < 8) {
            mx = sh[tid];
#pragma unroll
            for (int o = 4; o > 0; o >>= 1) mx = fmaxf(mx, __shfl_down_sync(0xffu, mx, o));
            if (tid == 0) s_bcast = mx;
        }
        __syncthreads();
        float gmax = s_bcast;

        float sm = 0.f;
        for (int i = tid; i < deg; i += 256) {
            int e = sorted[beg + i];
            sm += __expf(elog[(size_t)e * H + h] - gmax);
        }
#pragma unroll
        for (int o = 16; o > 0; o >>= 1) sm += __shfl_down_sync(0xffffffffu, sm, o);
        if ((tid & 31) == 0) sh[tid >> 5] = sm;
        __syncthreads();
        if (tid < 8) {
            sm = sh[tid];
#pragma unroll
            for (int o = 4; o > 0; o >>= 1) sm += __shfl_down_sync(0xffu, sm, o);
            if (tid == 0) s_bcast = sm;
        }
        __syncthreads();
        float inv = 1.f / (s_bcast + 1e-16f);

        float acc = 0.f;
        for (int base = 0; base < deg; base += 256) {
            __syncthreads();
            int i = base + tid;
            if (i < deg) {
                int e = sorted[beg + i];
                s_alpha[tid] = __expf(elog[(size_t)e * H + h] - gmax) * inv;
                s_row[tid]   = src[e];
            }
            __syncthreads();
            int lim = deg - base; if (lim > 256) lim = 256;
            for (int j = 0; j < lim; j++) {
                acc += s_alpha[j] * xp[(size_t)s_row[j] * HC + h * CDIM + tid];
            }
        }
        out[(size_t)d * HC + h * CDIM + tid] = fmaxf(acc + bias[h * CDIM + tid], 0.f);
        __syncthreads();
    }
}

// --------------------------------- host -------------------------------------
static void run_gemm(cudaStream_t st, const float* A, const float* B, int bRowMajor,
                     const float* bias, float* C, int M, int N, int K, bool relu) {
    dim3 grid((N + BN - 1) / BN, (M + BM - 1) / BM);
    mma_gemm_kernel<<<grid, 256, 0, st>>>(M, N, K, A, B, bRowMajor, bias, C,
                                          relu ? 1 : 0);
}

static void run_tower(cudaStream_t st,
                      const float* x, int N, int E, const int* src, const int* dst,
                      const float* W1, const float* a1s, const float* a1d, const float* b1,
                      const float* W2, const float* a2s, const float* a2d, const float* b2,
                      const float* lw1, const float* lb1, const float* lw2, const float* lb2,
                      const float* lw3, const float* lb3, float* xfin,
                      float* bufA, float* bufB, float* bufC, float* als, float* ald,
                      float* elog, int* deg, int* off, int* cur, int* sorted) {
    // big gemm kept as this tower's launch #4 (0-based #3 = ncu capture slot)
    zero_int_kernel<<<(N + 256) / 256, 256, 0, st>>>(deg, N + 1);
    zero_int_kernel<<<(N + 255) / 256, 256, 0, st>>>(cur, N);
    hist_kernel<<<(E + 255) / 256, 256, 0, st>>>(dst, E, deg);
    run_gemm(st, x, W1, 1, nullptr, bufA, N, 512, 256, false);   // ncu slot
    scan_kernel<<<1, 1024, 0, st>>>(deg, off, N);
    scatter_kernel<<<(E + 255) / 256, 256, 0, st>>>(dst, E, off, cur, sorted);

    compute_al<<<N, 256, 0, st>>>(bufA, a1s, a1d, als, ald, 2);
    edge_logits<<<(E + 255) / 256, 256, 0, st>>>(src, dst, als, ald, elog, E, 2);
    gat_aggregate<<<N, 256, 0, st>>>(bufA, elog, src, sorted, off, b1, bufB, 2);

    run_gemm(st, bufB, W2, 1, nullptr, bufA, N, 256, 512, false);
    compute_al<<<N, 256, 0, st>>>(bufA, a2s, a2d, als, ald, 1);
    edge_logits<<<(E + 255) / 256, 256, 0, st>>>(src, dst, als, ald, elog, E, 1);
    gat_aggregate<<<N, 256, 0, st>>>(bufA, elog, src, sorted, off, b2, bufC, 1);

    run_gemm(st, bufC, lw1, 1, lb1, bufA, N, 256, 256, true);
    run_gemm(st, bufA, lw2, 1, lb2, bufB, N, 128, 256, true);
    run_gemm(st, bufB, lw3, 1, lb3, xfin, N, 64, 128, true);
}

extern "C" void kernel_launch(void* const* d_in, const int* in_sizes, int n_in,
                              void* d_out, int out_size) {
    const float* x_m  = (const float*)d_in[0];
    const float* x_d  = (const float*)d_in[1];
    const int*   eix  = (const int*)d_in[2];
    const int*   eiy  = (const int*)d_in[3];
    const float* Wx1 = (const float*)d_in[4];
    const float* ax1s = (const float*)d_in[5];
    const float* ax1d = (const float*)d_in[6];
    const float* bx1 = (const float*)d_in[7];
    const float* Wx2 = (const float*)d_in[8];
    const float* ax2s = (const float*)d_in[9];
    const float* ax2d = (const float*)d_in[10];
    const float* bx2 = (const float*)d_in[11];
    const float* Wy1 = (const float*)d_in[12];
    const float* ay1s = (const float*)d_in[13];
    const float* ay1d = (const float*)d_in[14];
    const float* by1 = (const float*)d_in[15];
    const float* Wy2 = (const float*)d_in[16];
    const float* ay2s = (const float*)d_in[17];
    const float* ay2d = (const float*)d_in[18];
    const float* by2 = (const float*)d_in[19];
    const float* lwx1 = (const float*)d_in[20];
    const float* lbx1 = (const float*)d_in[21];
    const float* lwx2 = (const float*)d_in[22];
    const float* lbx2 = (const float*)d_in[23];
    const float* lwx3 = (const float*)d_in[24];
    const float* lbx3 = (const float*)d_in[25];
    const float* lwy1 = (const float*)d_in[26];
    const float* lby1 = (const float*)d_in[27];
    const float* lwy2 = (const float*)d_in[28];
    const float* lby2 = (const float*)d_in[29];
    const float* lwy3 = (const float*)d_in[30];
    const float* lby3 = (const float*)d_in[31];

    int M  = in_sizes[0] / 256;
    int D  = in_sizes[1] / 256;
    int EX = in_sizes[2] / 2;
    int EY = in_sizes[3] / 2;

    float *bufA, *bufB, *bufC, *als, *ald, *elog, *xfin;
    int *deg, *off, *cur, *sorted;
    float *bufA2, *bufB2, *bufC2, *als2, *ald2, *elog2, *yfin;
    int *deg2, *off2, *cur2, *sorted2;
    cudaGetSymbolAddress((void**)&bufA, g_bufA);
    cudaGetSymbolAddress((void**)&bufB, g_bufB);
    cudaGetSymbolAddress((void**)&bufC, g_bufC);
    cudaGetSymbolAddress((void**)&als, g_als);
    cudaGetSymbolAddress((void**)&ald, g_ald);
    cudaGetSymbolAddress((void**)&elog, g_elog);
    cudaGetSymbolAddress((void**)&deg, g_deg);
    cudaGetSymbolAddress((void**)&off, g_off);
    cudaGetSymbolAddress((void**)&cur, g_cur);
    cudaGetSymbolAddress((void**)&sorted, g_sorted);
    cudaGetSymbolAddress((void**)&xfin, g_xfin);
    cudaGetSymbolAddress((void**)&bufA2, g2_bufA);
    cudaGetSymbolAddress((void**)&bufB2, g2_bufB);
    cudaGetSymbolAddress((void**)&bufC2, g2_bufC);
    cudaGetSymbolAddress((void**)&als2, g2_als);
    cudaGetSymbolAddress((void**)&ald2, g2_ald);
    cudaGetSymbolAddress((void**)&elog2, g2_elog);
    cudaGetSymbolAddress((void**)&deg2, g2_deg);
    cudaGetSymbolAddress((void**)&off2, g2_off);
    cudaGetSymbolAddress((void**)&cur2, g2_cur);
    cudaGetSymbolAddress((void**)&sorted2, g2_sorted);
    cudaGetSymbolAddress((void**)&yfin, g_yfin);

    cudaStream_t sY;
    cudaStreamCreateWithFlags(&sY, cudaStreamNonBlocking);
    cudaEvent_t evRoot, evY;
    cudaEventCreateWithFlags(&evRoot, cudaEventDisableTiming);
    cudaEventCreateWithFlags(&evY, cudaEventDisableTiming);

    cudaEventRecord(evRoot, 0);
    cudaStreamWaitEvent(sY, evRoot, 0);

    run_tower(0, x_m, M, EX, eix, eix + EX,
              Wx1, ax1s, ax1d, bx1, Wx2, ax2s, ax2d, bx2,
              lwx1, lbx1, lwx2, lbx2, lwx3, lbx3, xfin,
              bufA, bufB, bufC, als, ald, elog, deg, off, cur, sorted);
    run_tower(sY, x_d, D, EY, eiy, eiy + EY,
              Wy1, ay1s, ay1d, by1, Wy2, ay2s, ay2d, by2,
              lwy1, lby1, lwy2, lby2, lwy3, lby3, yfin,
              bufA2, bufB2, bufC2, als2, ald2, elog2, deg2, off2, cur2, sorted2);

    cudaEventRecord(evY, sY);
    cudaStreamWaitEvent(0, evY, 0);

    run_gemm(0, xfin, yfin, 0, nullptr, (float*)d_out, M, D, 64, false);
}

// round 7
// speedup vs baseline: 1.4882x; 1.4882x over previous
#include <cuda_runtime.h>
#include <cuda_bf16.h>
#include <math.h>
#include <stdint.h>

// ----------------------------------------------------------------------------
// Problem constants: M=D=10000, FG=FD=256, H1=2, K=64, E=320000
// ----------------------------------------------------------------------------
#define MAXN 10000
#define MAXE 320000
#define CDIM 256

// ------------------------- device scratch (no mallocs) ----------------------
// Tower X
__device__ float g_bufA[MAXN * 512];          // xp (plain)
__device__ float g_xs_hi[MAXN * 256];
__device__ float g_xs_lo[MAXN * 256];
__device__ float g_aggB_hi[MAXN * 512];
__device__ float g_aggB_lo[MAXN * 512];
__device__ float g_aggC_hi[MAXN * 256];
__device__ float g_aggC_lo[MAXN * 256];
__device__ float g_m1_hi[MAXN * 256];
__device__ float g_m1_lo[MAXN * 256];
__device__ float g_m2_hi[MAXN * 128];
__device__ float g_m2_lo[MAXN * 128];
__device__ float g_fin_hi[MAXN * 64];
__device__ float g_fin_lo[MAXN * 64];
__device__ float g_als[MAXN * 2];
__device__ float g_ald[MAXN * 2];
__device__ float g_elog[MAXE * 2];
__device__ int   g_deg[MAXN + 1];
__device__ int   g_off[MAXN + 1];
__device__ int   g_cur[MAXN];
__device__ int   g_sorted[MAXE];
__device__ float4 g_pW1[65536];
__device__ float4 g_pW2[65536];
__device__ float4 g_pL1[32768];
__device__ float4 g_pL2[16384];
__device__ float4 g_pL3[8192];
// Tower Y
__device__ float g2_bufA[MAXN * 512];
__device__ float g2_xs_hi[MAXN * 256];
__device__ float g2_xs_lo[MAXN * 256];
__device__ float g2_aggB_hi[MAXN * 512];
__device__ float g2_aggB_lo[MAXN * 512];
__device__ float g2_aggC_hi[MAXN * 256];
__device__ float g2_aggC_lo[MAXN * 256];
__device__ float g2_m1_hi[MAXN * 256];
__device__ float g2_m1_lo[MAXN * 256];
__device__ float g2_m2_hi[MAXN * 128];
__device__ float g2_m2_lo[MAXN * 128];
__device__ float g2_fin_hi[MAXN * 64];
__device__ float g2_fin_lo[MAXN * 64];
__device__ float g2_als[MAXN * 2];
__device__ float g2_ald[MAXN * 2];
__device__ float g2_elog[MAXE * 2];
__device__ int   g2_deg[MAXN + 1];
__device__ int   g2_off[MAXN + 1];
__device__ int   g2_cur[MAXN];
__device__ int   g2_sorted[MAXE];
__device__ float4 g2_pW1[65536];
__device__ float4 g2_pW2[65536];
__device__ float4 g2_pL1[32768];
__device__ float4 g2_pL2[16384];
__device__ float4 g2_pL3[8192];
// final GEMM packed B (from Y tower fin)
__device__ float4 g_pFin[4 * 79 * 1024];

// ------------------------------ helpers -------------------------------------
__device__ __forceinline__ float tf32_rn(float a) {
    uint32_t u;
    asm("cvt.rna.tf32.f32 %0, %1;" : "=r"(u) : "f"(a));
    return __uint_as_float(u);
}

__device__ __forceinline__ void mma_m16n8k8(float* c, const uint32_t* a,
                                            const uint32_t* b) {
    asm volatile(
        "mma.sync.aligned.m16n8k8.row.col.f32.tf32.tf32.f32 "
        "{%0,%1,%2,%3}, {%4,%5,%6,%7}, {%8,%9}, {%0,%1,%2,%3};"
        : "+f"(c[0]), "+f"(c[1]), "+f"(c[2]), "+f"(c[3])
        : "r"(a[0]), "r"(a[1]), "r"(a[2]), "r"(a[3]), "r"(b[0]), "r"(b[1]));
}

__device__ __forceinline__ void cp16(uint32_t dst, const float* src, int sz) {
    asm volatile("cp.async.cg.shared.global [%0], [%1], 16, %2;"
                 :: "r"(dst), "l"(src), "r"(sz));
}
#define CP_COMMIT() asm volatile("cp.async.commit_group;" ::: "memory")

// ------------------------------ tiny kernels --------------------------------
__global__ void zero_int_kernel(int* p, int n) {
    int i = blockIdx.x * blockDim.x + threadIdx.x;
    if (i < n) p[i] = 0;
}

__global__ void hist_kernel(const int* __restrict__ dst, int E, int* __restrict__ deg) {
    int e = blockIdx.x * blockDim.x + threadIdx.x;
    if (e < E) atomicAdd(&deg[dst[e]], 1);
}

__global__ void scan_kernel(const int* __restrict__ deg, int* __restrict__ off, int n) {
    const int T = 1024;
    int t = threadIdx.x;
    int chunk = (n + T - 1) / T;
    int b = t * chunk;
    int e2 = b + chunk; if (e2 > n) e2 = n;
    int s = 0;
    for (int i = b; i < e2; i++) s += deg[i];
    __shared__ int sh[T];
    sh[t] = s;
    __syncthreads();
    for (int d2 = 1; d2 < T; d2 <<= 1) {
        int v = (t >= d2) ? sh[t - d2] : 0;
        __syncthreads();
        sh[t] += v;
        __syncthreads();
    }
    int run = (t == 0) ? 0 : sh[t - 1];
    for (int i = b; i < e2; i++) { off[i] = run; run += deg[i]; }
    if (t == 0) off[n] = sh[T - 1];
}

__global__ void scatter_kernel(const int* __restrict__ dst, int E,
                               const int* __restrict__ off, int* __restrict__ cur,
                               int* __restrict__ sorted) {
    int e = blockIdx.x * blockDim.x + threadIdx.x;
    if (e < E) {
        int d = dst[e];
        int p = atomicAdd(&cur[d], 1);
        sorted[off[d] + p] = e;
    }
}

// elementwise tf32 hi/lo split (n % 4 == 0)
__global__ void split_kernel(const float* __restrict__ in, float* __restrict__ hi,
                             float* __restrict__ lo, int n4) {
    int i = blockIdx.x * blockDim.x + threadIdx.x;
    if (i >= n4) return;
    float4 v = ((const float4*)in)[i];
    float4 h, l;
    h.x = tf32_rn(v.x); l.x = tf32_rn(v.x - h.x);
    h.y = tf32_rn(v.y); l.y = tf32_rn(v.y - h.y);
    h.z = tf32_rn(v.z); l.z = tf32_rn(v.z - h.z);
    h.w = tf32_rn(v.w); l.w = tf32_rn(v.w - h.w);
    ((float4*)hi)[i] = h;
    ((float4*)lo)[i] = l;
}

// pack weight W [K,N] row-major into fragment-major tiles:
// blob (t*KC + c): 1024 float4; f = (s*4+q)*128 + (bn ^ 2q);
// value = {hi W[k][gn], hi W[k+4][gn], lo W[k][gn], lo W[k+4][gn]}
__global__ void pack_w_kernel(const float* __restrict__ W, int K, int N, int NT,
                              float4* __restrict__ out, int total) {
    int idx = blockIdx.x * blockDim.x + threadIdx.x;
    if (idx >= total) return;
    int KC = K >> 4;
    int t = idx / (KC * 1024);
    int rem = idx - t * KC * 1024;
    int c = rem >> 10, f = rem & 1023;
    int s = f >> 9, q = (f >> 7) & 3, bns = f & 127;
    int bn = bns ^ (q << 1);
    int gn = t * 128 + bn;
    int k = c * 16 + s * 8 + q;
    float4 v = make_float4(0.f, 0.f, 0.f, 0.f);
    if (gn < N) {
        float w0 = W[(size_t)k * N + gn];
        float w4 = W[(size_t)(k + 4) * N + gn];
        float h0 = tf32_rn(w0), h4 = tf32_rn(w4);
        v = make_float4(h0, h4, tf32_rn(w0 - h0), tf32_rn(w4 - h4));
    }
    out[idx] = v;
}

// pack fin (pre-split [D,64] hi/lo) as B^T [K=64, D] fragment-major
__global__ void pack_fin_kernel(const float* __restrict__ fhi,
                                const float* __restrict__ flo,
                                int D, float4* __restrict__ out, int total) {
    int idx = blockIdx.x * blockDim.x + threadIdx.x;
    if (idx >= total) return;
    const int KC = 4;
    int t = idx / (KC * 1024);
    int rem = idx - t * KC * 1024;
    int c = rem >> 10, f = rem & 1023;
    int s = f >> 9, q = (f >> 7) & 3, bns = f & 127;
    int bn = bns ^ (q << 1);
    int gn = t * 128 + bn;
    int k = c * 16 + s * 8 + q;
    float4 v = make_float4(0.f, 0.f, 0.f, 0.f);
    if (gn < D) {
        v.x = fhi[(size_t)gn * 64 + k];
        v.y = fhi[(size_t)gn * 64 + k + 4];
        v.z = flo[(size_t)gn * 64 + k];
        v.w = flo[(size_t)gn * 64 + k + 4];
    }
    out[idx] = v;
}

// ------------------------ tf32x3 GEMM via mma.sync --------------------------
// C[M,N] = A @ B. A pre-split (Ahi/Alo [M,K] row-major). B pre-packed
// fragment-major (pack_w/pack_fin). 3-stage cp.async pipeline, one sync/chunk.
// Stage: AsH 2560 f + AsL 2560 f + Bs 1024 f4 = 9216 floats = 36864 B; x3.
#define GEMM_SMEM (3 * 9216 * 4)

__global__ __launch_bounds__(256, 2)
void mma_gemm_kernel(int M, int N, int K,
                     const float* __restrict__ Ahi, const float* __restrict__ Alo,
                     const float4* __restrict__ Bp,
                     const float* __restrict__ bias,
                     float* __restrict__ C,
                     float* __restrict__ Chi, float* __restrict__ Clo,
                     int doRelu) {
    extern __shared__ float smemf[];
    int tid = threadIdx.x, lane = tid & 31, wid = tid >> 5;
    int mBase = blockIdx.y * 128, nBase = blockIdx.x * 128;
    int wm = (wid & 3) * 32, wn = (wid >> 2) * 64;
    int KC = K >> 4;
    int cRow = tid >> 1, cS = tid & 1;

    float acc[2][8][4];
#pragma unroll
    for (int i = 0; i < 2; i++)
#pragma unroll
        for (int j = 0; j < 8; j++)
#pragma unroll
            for (int l = 0; l < 4; l++) acc[i][j][l] = 0.f;

    int gm = mBase + cRow;
    int gmc = gm < M ? gm : M - 1;
    int asz = gm < M ? 16 : 0;
    const float* srcHbase = &Ahi[(size_t)gmc * K + cS * 8];
    const float* srcLbase = &Alo[(size_t)gmc * K + cS * 8];

    auto do_copy = [&](int ch, int st) {
        float* AsH = smemf + st * 9216;
        float* AsL = AsH + 2560;
        uint32_t dH = (uint32_t)__cvta_generic_to_shared(&AsH[cRow * 20 + cS * 8]);
        uint32_t dL = (uint32_t)__cvta_generic_to_shared(&AsL[cRow * 20 + cS * 8]);
        int k0 = ch << 4;
        cp16(dH, srcHbase + k0, asz);
        cp16(dH + 16, srcHbase + k0 + 4, asz);
        cp16(dL, srcLbase + k0, asz);
        cp16(dL + 16, srcLbase + k0 + 4, asz);
        const float4* bsrc = Bp + ((size_t)blockIdx.x * KC + ch) * 1024;
        uint32_t dB = (uint32_t)__cvta_generic_to_shared(AsH + 5120);
#pragma unroll
        for (int i = 0; i < 4; i++)
            cp16(dB + (tid + i * 256) * 16, (const float*)(bsrc + tid + i * 256), 16);
    };

    do_copy(0, 0); CP_COMMIT();
    do_copy(1, 1); CP_COMMIT();

    for (int ch = 0; ch < KC; ch++) {
        if (ch == KC - 1)
            asm volatile("cp.async.wait_group 0;" ::: "memory");
        else
            asm volatile("cp.async.wait_group 1;" ::: "memory");
        __syncthreads();

        int st = ch % 3;
        const float* AsH = smemf + st * 9216;
        const float* AsL = AsH + 2560;
        const float4* Bs4 = (const float4*)(AsH + 5120);

#pragma unroll
        for (int s = 0; s < 2; s++) {
            int kq = lane & 3;
            uint32_t ah[2][4], al[2][4];
#pragma unroll
            for (int mt = 0; mt < 2; mt++) {
                int r = wm + (lane >> 2) + mt * 16;
                int o1 = r * 20 + s * 8 + kq;
                int o2 = (r + 8) * 20 + s * 8 + kq;
                ah[mt][0] = __float_as_uint(AsH[o1]);
                ah[mt][1] = __float_as_uint(AsH[o2]);
                ah[mt][2] = __float_as_uint(AsH[o1 + 4]);
                ah[mt][3] = __float_as_uint(AsH[o2 + 4]);
                al[mt][0] = __float_as_uint(AsL[o1]);
                al[mt][1] = __float_as_uint(AsL[o2]);
                al[mt][2] = __float_as_uint(AsL[o1 + 4]);
                al[mt][3] = __float_as_uint(AsL[o2 + 4]);
            }
            uint32_t bh[8][2], bl[8][2];
#pragma unroll
            for (int nt = 0; nt < 8; nt++) {
                int bn = wn + nt * 8 + (lane >> 2);
                float4 g = Bs4[(s * 4 + kq) * 128 + (bn ^ (kq << 1))];
                bh[nt][0] = __float_as_uint(g.x);
                bh[nt][1] = __float_as_uint(g.y);
                bl[nt][0] = __float_as_uint(g.z);
                bl[nt][1] = __float_as_uint(g.w);
            }
#pragma unroll
            for (int nt = 0; nt < 8; nt++)
#pragma unroll
                for (int mt = 0; mt < 2; mt++)
                    mma_m16n8k8(acc[mt][nt], ah[mt], bh[nt]);
#pragma unroll
            for (int nt = 0; nt < 8; nt++)
#pragma unroll
                for (int mt = 0; mt < 2; mt++)
                    mma_m16n8k8(acc[mt][nt], al[mt], bh[nt]);
#pragma unroll
            for (int nt = 0; nt < 8; nt++)
#pragma unroll
                for (int mt = 0; mt < 2; mt++)
                    mma_m16n8k8(acc[mt][nt], ah[mt], bl[nt]);
        }

        if (ch + 2 < KC) do_copy(ch + 2, (ch + 2) % 3);
        CP_COMMIT();
    }

    // epilogue
#pragma unroll
    for (int mt = 0; mt < 2; mt++) {
        int r0 = mBase + wm + mt * 16 + (lane >> 2);
        int r1 = r0 + 8;
#pragma unroll
        for (int nt = 0; nt < 8; nt++) {
            int c = nBase + wn + nt * 8 + (lane & 3) * 2;
            if (c >= N) continue;
            float b0 = bias ? bias[c] : 0.f;
            float b1 = bias ? bias[c + 1] : 0.f;
#pragma unroll
            for (int half = 0; half < 2; half++) {
                int r = half ? r1 : r0;
                if (r >= M) continue;
                float v0 = acc[mt][nt][half * 2 + 0] + b0;
                float v1 = acc[mt][nt][half * 2 + 1] + b1;
                if (doRelu) { v0 = fmaxf(v0, 0.f); v1 = fmaxf(v1, 0.f); }
                if (C) *(float2*)&C[(size_t)r * N + c] = make_float2(v0, v1);
                if (Chi) {
                    float h0 = tf32_rn(v0), h1 = tf32_rn(v1);
                    *(float2*)&Chi[(size_t)r * N + c] = make_float2(h0, h1);
                    *(float2*)&Clo[(size_t)r * N + c] =
                        make_float2(tf32_rn(v0 - h0), tf32_rn(v1 - h1));
                }
            }
        }
    }
}

// --------------------------- GAT-specific kernels ---------------------------
__global__ void compute_al(const float* __restrict__ xp,
                           const float* __restrict__ asrc, const float* __restrict__ adst,
                           float* __restrict__ als, float* __restrict__ ald, int H) {
    int n = blockIdx.x, tid = threadIdx.x;
    int HC = H * CDIM;
    __shared__ float sh1[8], sh2[8];
    for (int h = 0; h < H; h++) {
        float v = xp[(size_t)n * HC + h * CDIM + tid];
        float s1 = v * asrc[h * CDIM + tid];
        float s2 = v * adst[h * CDIM + tid];
#pragma unroll
        for (int o = 16; o > 0; o >>= 1) {
            s1 += __shfl_down_sync(0xffffffffu, s1, o);
            s2 += __shfl_down_sync(0xffffffffu, s2, o);
        }
        if ((tid & 31) == 0) { sh1[tid >> 5] = s1; sh2[tid >> 5] = s2; }
        __syncthreads();
        if (tid < 8) {
            s1 = sh1[tid]; s2 = sh2[tid];
#pragma unroll
            for (int o = 4; o > 0; o >>= 1) {
                s1 += __shfl_down_sync(0xffu, s1, o);
                s2 += __shfl_down_sync(0xffu, s2, o);
            }
            if (tid == 0) { als[n * H + h] = s1; ald[n * H + h] = s2; }
        }
        __syncthreads();
    }
}

__global__ void edge_logits(const int* __restrict__ src, const int* __restrict__ dst,
                            const float* __restrict__ als, const float* __restrict__ ald,
                            float* __restrict__ elog, int E, int H) {
    int e = blockIdx.x * blockDim.x + threadIdx.x;
    if (e >= E) return;
    int s = src[e], d = dst[e];
    for (int h = 0; h < H; h++) {
        float v = als[s * H + h] + ald[d * H + h];
        elog[(size_t)e * H + h] = v > 0.f ? v : 0.2f * v;
    }
}

// aggregate writes tf32 hi/lo split outputs (consumed only by GEMMs)
__global__ void gat_aggregate(const float* __restrict__ xp, const float* __restrict__ elog,
                              const int* __restrict__ src, const int* __restrict__ sorted,
                              const int* __restrict__ off, const float* __restrict__ bias,
                              float* __restrict__ out_hi, float* __restrict__ out_lo,
                              int H) {
    int d = blockIdx.x, tid = threadIdx.x;
    int beg = off[d];
    int deg = off[d + 1] - beg;
    int HC = H * CDIM;
    __shared__ float sh[8];
    __shared__ float s_bcast;
    __shared__ float s_alpha[256];
    __shared__ int   s_row[256];

    if (deg <= 256) {
        if (tid < deg) s_row[tid] = src[sorted[beg + tid]];
        for (int h = 0; h < H; h++) {
            float mx = -1e30f;
            if (tid < deg) mx = elog[(size_t)sorted[beg + tid] * H + h];
#pragma unroll
            for (int o = 16; o > 0; o >>= 1)
                mx = fmaxf(mx, __shfl_down_sync(0xffffffffu, mx, o));
            if ((tid & 31) == 0) sh[tid >> 5] = mx;
            __syncthreads();
            if (tid < 8) {
                mx = sh[tid];
#pragma unroll
                for (int o = 4; o > 0; o >>= 1)
                    mx = fmaxf(mx, __shfl_down_sync(0xffu, mx, o));
                if (tid == 0) s_bcast = mx;
            }
            __syncthreads();
            float gmax = s_bcast;

            float ee = 0.f;
            if (tid < deg)
                ee = __expf(elog[(size_t)sorted[beg + tid] * H + h] - gmax);
            s_alpha[tid] = ee;
            float sm = ee;
#pragma unroll
            for (int o = 16; o > 0; o >>= 1) sm += __shfl_down_sync(0xffffffffu, sm, o);
            if ((tid & 31) == 0) sh[tid >> 5] = sm;
            __syncthreads();
            if (tid < 8) {
                sm = sh[tid];
#pragma unroll
                for (int o = 4; o > 0; o >>= 1) sm += __shfl_down_sync(0xffu, sm, o);
                if (tid == 0) s_bcast = sm;
            }
            __syncthreads();
            float inv = 1.f / (s_bcast + 1e-16f);

            const float* xph = xp + h * CDIM + tid;
            float a0 = 0.f, a1 = 0.f, a2 = 0.f, a3 = 0.f;
            int j = 0;
            for (; j + 4 <= deg; j += 4) {
                a0 += s_alpha[j + 0] * xph[(size_t)s_row[j + 0] * HC];
                a1 += s_alpha[j + 1] * xph[(size_t)s_row[j + 1] * HC];
                a2 += s_alpha[j + 2] * xph[(size_t)s_row[j + 2] * HC];
                a3 += s_alpha[j + 3] * xph[(size_t)s_row[j + 3] * HC];
            }
            for (; j < deg; j++)
                a0 += s_alpha[j] * xph[(size_t)s_row[j] * HC];
            float v = fmaxf(((a0 + a1) + (a2 + a3)) * inv + bias[h * CDIM + tid], 0.f);
            float hv = tf32_rn(v);
            out_hi[(size_t)d * HC + h * CDIM + tid] = hv;
            out_lo[(size_t)d * HC + h * CDIM + tid] = tf32_rn(v - hv);
            __syncthreads();
        }
        return;
    }

    for (int h = 0; h < H; h++) {
        float mx = -1e30f;
        for (int i = tid; i < deg; i += 256) {
            int e = sorted[beg + i];
            mx = fmaxf(mx, elog[(size_t)e * H + h]);
        }
#pragma unroll
        for (int o = 16; o > 0; o >>= 1) mx = fmaxf(mx, __shfl_down_sync(0xffffffffu, mx, o));
        if ((tid & 31) == 0) sh[tid >> 5] = mx;
        __syncthreads();
        if (tid < 8) {
            mx = sh[tid];
#pragma unroll
            for (int o = 4; o > 0; o >>= 1) mx = fmaxf(mx, __shfl_down_sync(0xffu, mx, o));
            if (tid == 0) s_bcast = mx;
        }
        __syncthreads();
        float gmax = s_bcast;

        float sm = 0.f;
        for (int i = tid; i < deg; i += 256) {
            int e = sorted[beg + i];
            sm += __expf(elog[(size_t)e * H + h] - gmax);
        }
#pragma unroll
        for (int o = 16; o > 0; o >>= 1) sm += __shfl_down_sync(0xffffffffu, sm, o);
        if ((tid & 31) == 0) sh[tid >> 5] = sm;
        __syncthreads();
        if (tid < 8) {
            sm = sh[tid];
#pragma unroll
            for (int o = 4; o > 0; o >>= 1) sm += __shfl_down_sync(0xffu, sm, o);
            if (tid == 0) s_bcast = sm;
        }
        __syncthreads();
        float inv = 1.f / (s_bcast + 1e-16f);

        float acc = 0.f;
        for (int base = 0; base < deg; base += 256) {
            __syncthreads();
            int i = base + tid;
            if (i < deg) {
                int e = sorted[beg + i];
                s_alpha[tid] = __expf(elog[(size_t)e * H + h] - gmax) * inv;
                s_row[tid]   = src[e];
            }
            __syncthreads();
            int lim = deg - base; if (lim > 256) lim = 256;
            for (int j = 0; j < lim; j++) {
                acc += s_alpha[j] * xp[(size_t)s_row[j] * HC + h * CDIM + tid];
            }
        }
        float v = fmaxf(acc + bias[h * CDIM + tid], 0.f);
        float hv = tf32_rn(v);
        out_hi[(size_t)d * HC + h * CDIM + tid] = hv;
        out_lo[(size_t)d * HC + h * CDIM + tid] = tf32_rn(v - hv);
        __syncthreads();
    }
}

// --------------------------------- host -------------------------------------
static void run_gemm(cudaStream_t st, const float* Ahi, const float* Alo,
                     const float4* Bp, const float* bias,
                     float* C, float* Chi, float* Clo,
                     int M, int N, int K, bool relu) {
    dim3 grid((N + 127) / 128, (M + 127) / 128);
    mma_gemm_kernel<<<grid, 256, GEMM_SMEM, st>>>(M, N, K, Ahi, Alo, Bp, bias,
                                                  C, Chi, Clo, relu ? 1 : 0);
}

static void run_pack_w(cudaStream_t st, const float* W, int K, int N, float4* out) {
    int NT = (N + 127) / 128;
    int total = (K >> 4) * NT * 1024;
    pack_w_kernel<<<(total + 255) / 256, 256, 0, st>>>(W, K, N, NT, out, total);
}

struct Tower {
    float *bufA, *xs_hi, *xs_lo, *aggB_hi, *aggB_lo, *aggC_hi, *aggC_lo;
    float *m1_hi, *m1_lo, *m2_hi, *m2_lo, *fin_hi, *fin_lo;
    float *als, *ald, *elog;
    int *deg, *off, *cur, *sorted;
    float4 *pW1, *pW2, *pL1, *pL2, *pL3;
};

static void run_tower(cudaStream_t st, const Tower& T,
                      const float* x, int N, int E, const int* src, const int* dst,
                      const float* W1, const float* a1s, const float* a1d, const float* b1,
                      const float* W2, const float* a2s, const float* a2d, const float* b2,
                      const float* lw1, const float* lb1, const float* lw2, const float* lb2,
                      const float* lw3, const float* lb3) {
    // [0..2] then GEMM1 at launch index 3 (ncu capture slot on X stream)
    split_kernel<<<(N * 256 / 4 + 255) / 256, 256, 0, st>>>(x, T.xs_hi, T.xs_lo,
                                                            N * 256 / 4);
    run_pack_w(st, W1, 256, 512, T.pW1);
    zero_int_kernel<<<(N + 256) / 256, 256, 0, st>>>(T.deg, N + 1);
    run_gemm(st, T.xs_hi, T.xs_lo, T.pW1, nullptr, T.bufA, nullptr, nullptr,
             N, 512, 256, false);                                   // ncu slot
    zero_int_kernel<<<(N + 255) / 256, 256, 0, st>>>(T.cur, N);
    hist_kernel<<<(E + 255) / 256, 256, 0, st>>>(dst, E, T.deg);
    scan_kernel<<<1, 1024, 0, st>>>(T.deg, T.off, N);
    scatter_kernel<<<(E + 255) / 256, 256, 0, st>>>(dst, E, T.off, T.cur, T.sorted);

    compute_al<<<N, 256, 0, st>>>(T.bufA, a1s, a1d, T.als, T.ald, 2);
    edge_logits<<<(E + 255) / 256, 256, 0, st>>>(src, dst, T.als, T.ald, T.elog, E, 2);
    gat_aggregate<<<N, 256, 0, st>>>(T.bufA, T.elog, src, T.sorted, T.off, b1,
                                     T.aggB_hi, T.aggB_lo, 2);

    run_pack_w(st, W2, 512, 256, T.pW2);
    run_gemm(st, T.aggB_hi, T.aggB_lo, T.pW2, nullptr, T.bufA, nullptr, nullptr,
             N, 256, 512, false);
    compute_al<<<N, 256, 0, st>>>(T.bufA, a2s, a2d, T.als, T.ald, 1);
    edge_logits<<<(E + 255) / 256, 256, 0, st>>>(src, dst, T.als, T.ald, T.elog, E, 1);
    gat_aggregate<<<N, 256, 0, st>>>(T.bufA, T.elog, src, T.sorted, T.off, b2,
                                     T.aggC_hi, T.aggC_lo, 1);

    run_pack_w(st, lw1, 256, 256, T.pL1);
    run_gemm(st, T.aggC_hi, T.aggC_lo, T.pL1, lb1, nullptr, T.m1_hi, T.m1_lo,
             N, 256, 256, true);
    run_pack_w(st, lw2, 256, 128, T.pL2);
    run_gemm(st, T.m1_hi, T.m1_lo, T.pL2, lb2, nullptr, T.m2_hi, T.m2_lo,
             N, 128, 256, true);
    run_pack_w(st, lw3, 128, 64, T.pL3);
    run_gemm(st, T.m2_hi, T.m2_lo, T.pL3, lb3, nullptr, T.fin_hi, T.fin_lo,
             N, 64, 128, true);
}

#define GSA(p, s) cudaGetSymbolAddress((void**)&(p), s)

extern "C" void kernel_launch(void* const* d_in, const int* in_sizes, int n_in,
                              void* d_out, int out_size) {
    const float* x_m  = (const float*)d_in[0];
    const float* x_d  = (const float*)d_in[1];
    const int*   eix  = (const int*)d_in[2];
    const int*   eiy  = (const int*)d_in[3];
    const float* Wx1 = (const float*)d_in[4];
    const float* ax1s = (const float*)d_in[5];
    const float* ax1d = (const float*)d_in[6];
    const float* bx1 = (const float*)d_in[7];
    const float* Wx2 = (const float*)d_in[8];
    const float* ax2s = (const float*)d_in[9];
    const float* ax2d = (const float*)d_in[10];
    const float* bx2 = (const float*)d_in[11];
    const float* Wy1 = (const float*)d_in[12];
    const float* ay1s = (const float*)d_in[13];
    const float* ay1d = (const float*)d_in[14];
    const float* by1 = (const float*)d_in[15];
    const float* Wy2 = (const float*)d_in[16];
    const float* ay2s = (const float*)d_in[17];
    const float* ay2d = (const float*)d_in[18];
    const float* by2 = (const float*)d_in[19];
    const float* lwx1 = (const float*)d_in[20];
    const float* lbx1 = (const float*)d_in[21];
    const float* lwx2 = (const float*)d_in[22];
    const float* lbx2 = (const float*)d_in[23];
    const float* lwx3 = (const float*)d_in[24];
    const float* lbx3 = (const float*)d_in[25];
    const float* lwy1 = (const float*)d_in[26];
    const float* lby1 = (const float*)d_in[27];
    const float* lwy2 = (const float*)d_in[28];
    const float* lby2 = (const float*)d_in[29];
    const float* lwy3 = (const float*)d_in[30];
    const float* lby3 = (const float*)d_in[31];

    int M  = in_sizes[0] / 256;
    int D  = in_sizes[1] / 256;
    int EX = in_sizes[2] / 2;
    int EY = in_sizes[3] / 2;

    cudaFuncSetAttribute(mma_gemm_kernel,
                         cudaFuncAttributeMaxDynamicSharedMemorySize, GEMM_SMEM);

    Tower TX, TY;
    GSA(TX.bufA, g_bufA); GSA(TX.xs_hi, g_xs_hi); GSA(TX.xs_lo, g_xs_lo);
    GSA(TX.aggB_hi, g_aggB_hi); GSA(TX.aggB_lo, g_aggB_lo);
    GSA(TX.aggC_hi, g_aggC_hi); GSA(TX.aggC_lo, g_aggC_lo);
    GSA(TX.m1_hi, g_m1_hi); GSA(TX.m1_lo, g_m1_lo);
    GSA(TX.m2_hi, g_m2_hi); GSA(TX.m2_lo, g_m2_lo);
    GSA(TX.fin_hi, g_fin_hi); GSA(TX.fin_lo, g_fin_lo);
    GSA(TX.als, g_als); GSA(TX.ald, g_ald); GSA(TX.elog, g_elog);
    GSA(TX.deg, g_deg); GSA(TX.off, g_off); GSA(TX.cur, g_cur);
    GSA(TX.sorted, g_sorted);
    GSA(TX.pW1, g_pW1); GSA(TX.pW2, g_pW2);
    GSA(TX.pL1, g_pL1); GSA(TX.pL2, g_pL2); GSA(TX.pL3, g_pL3);

    GSA(TY.bufA, g2_bufA); GSA(TY.xs_hi, g2_xs_hi); GSA(TY.xs_lo, g2_xs_lo);
    GSA(TY.aggB_hi, g2_aggB_hi); GSA(TY.aggB_lo, g2_aggB_lo);
    GSA(TY.aggC_hi, g2_aggC_hi); GSA(TY.aggC_lo, g2_aggC_lo);
    GSA(TY.m1_hi, g2_m1_hi); GSA(TY.m1_lo, g2_m1_lo);
    GSA(TY.m2_hi, g2_m2_hi); GSA(TY.m2_lo, g2_m2_lo);
    GSA(TY.fin_hi, g2_fin_hi); GSA(TY.fin_lo, g2_fin_lo);
    GSA(TY.als, g2_als); GSA(TY.ald, g2_ald); GSA(TY.elog, g2_elog);
    GSA(TY.deg, g2_deg); GSA(TY.off, g2_off); GSA(TY.cur, g2_cur);
    GSA(TY.sorted, g2_sorted);
    GSA(TY.pW1, g2_pW1); GSA(TY.pW2, g2_pW2);
    GSA(TY.pL1, g2_pL1); GSA(TY.pL2, g2_pL2); GSA(TY.pL3, g2_pL3);

    float4* pFin;
    GSA(pFin, g_pFin);

    cudaStream_t sY;
    cudaStreamCreateWithFlags(&sY, cudaStreamNonBlocking);
    cudaEvent_t evRoot, evY;
    cudaEventCreateWithFlags(&evRoot, cudaEventDisableTiming);
    cudaEventCreateWithFlags(&evY, cudaEventDisableTiming);

    cudaEventRecord(evRoot, 0);
    cudaStreamWaitEvent(sY, evRoot, 0);

    run_tower(0, TX, x_m, M, EX, eix, eix + EX,
              Wx1, ax1s, ax1d, bx1, Wx2, ax2s, ax2d, bx2,
              lwx1, lbx1, lwx2, lbx2, lwx3, lbx3);
    run_tower(sY, TY, x_d, D, EY, eiy, eiy + EY,
              Wy1, ay1s, ay1d, by1, Wy2, ay2s, ay2d, by2,
              lwy1, lby1, lwy2, lby2, lwy3, lby3);

    // pack Y-tower fin as B^T for the final GEMM (on Y stream), then join
    int finTotal = 4 * ((D + 127) / 128) * 1024;
    pack_fin_kernel<<<(finTotal + 255) / 256, 256, 0, sY>>>(TY.fin_hi, TY.fin_lo,
                                                            D, pFin, finTotal);
    cudaEventRecord(evY, sY);
    cudaStreamWaitEvent(0, evY, 0);

    run_gemm(0, TX.fin_hi, TX.fin_lo, pFin, nullptr,
             (float*)d_out, nullptr, nullptr, M, D, 64, false);
}

// round 8
// speedup vs baseline: 2.1893x; 1.4711x over previous
#include <cuda_runtime.h>
#include <cuda_fp16.h>
#include <math.h>
#include <stdint.h>

// ----------------------------------------------------------------------------
// Problem constants: M=D=10000, FG=FD=256, H1=2, K=64, E=320000
// ----------------------------------------------------------------------------
#define MAXN 10000
#define MAXE 320000
#define CDIM 256

// ------------------------- device scratch (no mallocs) ----------------------
// Packed panel buffers (uint4 per (row,kq): {h2(k0),h2(k0+8),l2(k0),l2(k0+8)})
// Tower X
__device__ float g_bufA[MAXN * 512];
__device__ uint4 g_xsP[650000];
__device__ uint4 g_aggBP[1300000];
__device__ uint4 g_aggCP[650000];
__device__ uint4 g_m1P[650000];
__device__ uint4 g_m2P[330000];
__device__ uint4 g_finP[165000];
__device__ float g_als[MAXN * 2];
__device__ float g_ald[MAXN * 2];
__device__ float g_elog[MAXE * 2];
__device__ int   g_deg[MAXN + 1];
__device__ int   g_off[MAXN + 1];
__device__ int   g_cur[MAXN];
__device__ int   g_sorted[MAXE];
__device__ uint4 g_pW1[32768];
__device__ uint4 g_pW2[32768];
__device__ uint4 g_pL1[16384];
__device__ uint4 g_pL2[8192];
__device__ uint4 g_pL3[4096];
// Tower Y
__device__ float g2_bufA[MAXN * 512];
__device__ uint4 g2_xsP[650000];
__device__ uint4 g2_aggBP[1300000];
__device__ uint4 g2_aggCP[650000];
__device__ uint4 g2_m1P[650000];
__device__ uint4 g2_m2P[330000];
__device__ uint4 g2_finP[165000];
__device__ float g2_als[MAXN * 2];
__device__ float g2_ald[MAXN * 2];
__device__ float g2_elog[MAXE * 2];
__device__ int   g2_deg[MAXN + 1];
__device__ int   g2_off[MAXN + 1];
__device__ int   g2_cur[MAXN];
__device__ int   g2_sorted[MAXE];
__device__ uint4 g2_pW1[32768];
__device__ uint4 g2_pW2[32768];
__device__ uint4 g2_pL1[16384];
__device__ uint4 g2_pL2[8192];
__device__ uint4 g2_pL3[4096];

// ------------------------------ helpers -------------------------------------
// split fp32 pair into fp16 hi-half2 / lo-half2 (packed uint32)
__device__ __forceinline__ void split_pair(float a, float b,
                                           uint32_t& hi, uint32_t& lo) {
    __half ha = __float2half_rn(a), hb = __float2half_rn(b);
    float ra = a - __half2float(ha), rb = b - __half2float(hb);
    __half2 h = __halves2half2(ha, hb);
    __half2 l = __floats2half2_rn(ra, rb);
    hi = *(uint32_t*)&h;
    lo = *(uint32_t*)&l;
}

__device__ __forceinline__ void mma_f16(float* c, const uint32_t* a,
                                        const uint32_t* b) {
    asm volatile(
        "mma.sync.aligned.m16n8k16.row.col.f32.f16.f16.f32 "
        "{%0,%1,%2,%3}, {%4,%5,%6,%7}, {%8,%9}, {%0,%1,%2,%3};"
        : "+f"(c[0]), "+f"(c[1]), "+f"(c[2]), "+f"(c[3])
        : "r"(a[0]), "r"(a[1]), "r"(a[2]), "r"(a[3]), "r"(b[0]), "r"(b[1]));
}

__device__ __forceinline__ void cp16(uint32_t dst, const void* src) {
    asm volatile("cp.async.cg.shared.global [%0], [%1], 16;"
                 :: "r"(dst), "l"(src));
}
#define CP_COMMIT() asm volatile("cp.async.commit_group;" ::: "memory")

// ------------------------------ tiny kernels --------------------------------
__global__ void zero_int_kernel(int* p, int n) {
    int i = blockIdx.x * blockDim.x + threadIdx.x;
    if (i < n) p[i] = 0;
}

__global__ void hist_kernel(const int* __restrict__ dst, int E, int* __restrict__ deg) {
    int e = blockIdx.x * blockDim.x + threadIdx.x;
    if (e < E) atomicAdd(&deg[dst[e]], 1);
}

__global__ void scan_kernel(const int* __restrict__ deg, int* __restrict__ off, int n) {
    const int T = 1024;
    int t = threadIdx.x;
    int chunk = (n + T - 1) / T;
    int b = t * chunk;
    int e2 = b + chunk; if (e2 > n) e2 = n;
    int s = 0;
    for (int i = b; i < e2; i++) s += deg[i];
    __shared__ int sh[T];
    sh[t] = s;
    __syncthreads();
    for (int d2 = 1; d2 < T; d2 <<= 1) {
        int v = (t >= d2) ? sh[t - d2] : 0;
        __syncthreads();
        sh[t] += v;
        __syncthreads();
    }
    int run = (t == 0) ? 0 : sh[t - 1];
    for (int i = b; i < e2; i++) { off[i] = run; run += deg[i]; }
    if (t == 0) off[n] = sh[T - 1];
}

__global__ void scatter_kernel(const int* __restrict__ dst, int E,
                               const int* __restrict__ off, int* __restrict__ cur,
                               int* __restrict__ sorted) {
    int e = blockIdx.x * blockDim.x + threadIdx.x;
    if (e < E) {
        int d = dst[e];
        int p = atomicAdd(&cur[d], 1);
        sorted[off[d] + p] = e;
    }
}

// pack fp32 activation matrix X [Nrows, K] row-major into A panels
__global__ void pack_x_kernel(const float* __restrict__ X, int Nrows, int K,
                              uint4* __restrict__ out, int total) {
    int idx = blockIdx.x * blockDim.x + threadIdx.x;
    if (idx >= total) return;
    int KC16 = K >> 4;
    int t = idx / (KC16 * 512);
    int rem = idx - t * (KC16 * 512);
    int c16 = rem >> 9, f = rem & 511;
    int kq = f >> 7, pos = f & 127;
    int r = pos ^ (kq << 1);
    int row = t * 128 + r;
    int k0 = c16 * 16 + kq * 2;
    uint4 v = make_uint4(0u, 0u, 0u, 0u);
    if (row < Nrows) {
        const float* p = &X[(size_t)row * K];
        split_pair(p[k0], p[k0 + 1], v.x, v.z);
        split_pair(p[k0 + 8], p[k0 + 9], v.y, v.w);
    }
    out[idx] = v;
}

// pack weight W [K, N] row-major into B panels (rows = n)
__global__ void pack_w_kernel(const float* __restrict__ W, int K, int N,
                              uint4* __restrict__ out, int total) {
    int idx = blockIdx.x * blockDim.x + threadIdx.x;
    if (idx >= total) return;
    int KC16 = K >> 4;
    int t = idx / (KC16 * 512);
    int rem = idx - t * (KC16 * 512);
    int c16 = rem >> 9, f = rem & 511;
    int kq = f >> 7, pos = f & 127;
    int n = t * 128 + (pos ^ (kq << 1));
    int k0 = c16 * 16 + kq * 2;
    uint4 v = make_uint4(0u, 0u, 0u, 0u);
    if (n < N) {
        split_pair(W[(size_t)k0 * N + n], W[(size_t)(k0 + 1) * N + n], v.x, v.z);
        split_pair(W[(size_t)(k0 + 8) * N + n], W[(size_t)(k0 + 9) * N + n], v.y, v.w);
    }
    out[idx] = v;
}

// ------------------------ fp16x3 GEMM via mma.sync --------------------------
// C[M,N] = A @ B; A,B pre-packed panels. 3-stage cp.async pipeline, stage = 32 k.
// Outputs: plain fp32 C (optional) and/or packed panels Cpack (optional).
#define GEMM_SMEM (3 * 2048 * 16)

__global__ __launch_bounds__(256, 2)
void mma_gemm_kernel(int M, int N, int K,
                     const uint4* __restrict__ Ap, const uint4* __restrict__ Bp,
                     const float* __restrict__ bias,
                     float* __restrict__ C,
                     uint4* __restrict__ Cpack, int KCpackTot,
                     int doRelu) {
    extern __shared__ uint4 smem4[];
    int tid = threadIdx.x, lane = tid & 31, wid = tid >> 5;
    int mBase = blockIdx.y * 128, nBase = blockIdx.x * 128;
    int wm = (wid & 3) * 32, wn = (wid >> 2) * 64;
    int KC16 = K >> 4, KCS = K >> 5;

    float acc[2][8][4];
#pragma unroll
    for (int i = 0; i < 2; i++)
#pragma unroll
        for (int j = 0; j < 8; j++)
#pragma unroll
            for (int l = 0; l < 4; l++) acc[i][j][l] = 0.f;

    const uint4* Asrc = Ap + (size_t)blockIdx.y * KC16 * 512;
    const uint4* Bsrc = Bp + (size_t)blockIdx.x * KC16 * 512;

    auto do_copy = [&](int chS, int st) {
        uint4* dst = smem4 + st * 2048;
        uint32_t dA = (uint32_t)__cvta_generic_to_shared(dst + tid);
        const uint4* sA = Asrc + chS * 1024 + tid;
#pragma unroll
        for (int i = 0; i < 4; i++)
            cp16(dA + i * 256 * 16, sA + i * 256);
        uint32_t dB = (uint32_t)__cvta_generic_to_shared(dst + 1024 + tid);
        const uint4* sB = Bsrc + chS * 1024 + tid;
#pragma unroll
        for (int i = 0; i < 4; i++)
            cp16(dB + i * 256 * 16, sB + i * 256);
    };

    do_copy(0, 0); CP_COMMIT();
    if (1 < KCS) { do_copy(1, 1); }
    CP_COMMIT();

    int kq = lane & 3, sx = kq << 1;
    int rquad = lane >> 2;

    for (int ch = 0; ch < KCS; ch++) {
        if (ch >= KCS - 2)
            asm volatile("cp.async.wait_group 0;" ::: "memory");
        else
            asm volatile("cp.async.wait_group 1;" ::: "memory");
        __syncthreads();

        const uint4* As = smem4 + (ch % 3) * 2048;
        const uint4* Bs = As + 1024;

#pragma unroll
        for (int c2 = 0; c2 < 2; c2++) {
            int base = c2 * 512 + kq * 128;
            uint32_t ah[2][4], al[2][4];
#pragma unroll
            for (int mt = 0; mt < 2; mt++) {
                int rr = wm + rquad + mt * 16;
                uint4 v0 = As[base + (rr ^ sx)];
                uint4 v1 = As[base + ((rr + 8) ^ sx)];
                ah[mt][0] = v0.x; ah[mt][1] = v1.x;
                ah[mt][2] = v0.y; ah[mt][3] = v1.y;
                al[mt][0] = v0.z; al[mt][1] = v1.z;
                al[mt][2] = v0.w; al[mt][3] = v1.w;
            }
#pragma unroll
            for (int hlf = 0; hlf < 2; hlf++) {
                uint32_t bh[4][2], bl[4][2];
#pragma unroll
                for (int j = 0; j < 4; j++) {
                    int bn = wn + (hlf * 4 + j) * 8 + rquad;
                    uint4 g = Bs[base + (bn ^ sx)];
                    bh[j][0] = g.x; bh[j][1] = g.y;
                    bl[j][0] = g.z; bl[j][1] = g.w;
                }
#pragma unroll
                for (int j = 0; j < 4; j++)
#pragma unroll
                    for (int mt = 0; mt < 2; mt++)
                        mma_f16(acc[mt][hlf * 4 + j], ah[mt], bh[j]);
#pragma unroll
                for (int j = 0; j < 4; j++)
#pragma unroll
                    for (int mt = 0; mt < 2; mt++)
                        mma_f16(acc[mt][hlf * 4 + j], al[mt], bh[j]);
#pragma unroll
                for (int j = 0; j < 4; j++)
#pragma unroll
                    for (int mt = 0; mt < 2; mt++)
                        mma_f16(acc[mt][hlf * 4 + j], ah[mt], bl[j]);
            }
        }

        if (ch + 2 < KCS) do_copy(ch + 2, (ch + 2) % 3);
        CP_COMMIT();
    }

    // ------------------------------ epilogue --------------------------------
#pragma unroll
    for (int mt = 0; mt < 2; mt++) {
        int r0loc = wm + mt * 16 + rquad;
        int gr0 = mBase + r0loc, gr1 = gr0 + 8;
        if (C) {
#pragma unroll
            for (int nt = 0; nt < 8; nt++) {
                int c = nBase + wn + nt * 8 + kq * 2;
                if (c >= N) continue;
                float b0 = bias ? bias[c] : 0.f;
                float b1 = bias ? bias[c + 1] : 0.f;
                if (gr0 < M) {
                    float v0 = acc[mt][nt][0] + b0, v1 = acc[mt][nt][1] + b1;
                    if (doRelu) { v0 = fmaxf(v0, 0.f); v1 = fmaxf(v1, 0.f); }
                    *(float2*)&C[(size_t)gr0 * N + c] = make_float2(v0, v1);
                }
                if (gr1 < M) {
                    float v2 = acc[mt][nt][2] + b0, v3 = acc[mt][nt][3] + b1;
                    if (doRelu) { v2 = fmaxf(v2, 0.f); v3 = fmaxf(v3, 0.f); }
                    *(float2*)&C[(size_t)gr1 * N + c] = make_float2(v2, v3);
                }
            }
        }
        if (Cpack) {
#pragma unroll
            for (int ntp = 0; ntp < 8; ntp += 2) {
                int ncol = nBase + wn + ntp * 8 + kq * 2;
                int c16 = ncol >> 4;
                if (c16 >= KCpackTot) continue;
                float b0 = bias ? bias[ncol] : 0.f;
                float b1 = bias ? bias[ncol + 1] : 0.f;
                float b8 = bias ? bias[ncol + 8] : 0.f;
                float b9 = bias ? bias[ncol + 9] : 0.f;
                size_t dbase = ((size_t)blockIdx.y * KCpackTot + c16) * 512 +
                               kq * 128;
#pragma unroll
                for (int hlf = 0; hlf < 2; hlf++) {
                    int rloc = r0loc + hlf * 8;
                    int grow = mBase + rloc;
                    uint4 v = make_uint4(0u, 0u, 0u, 0u);
                    if (grow < M) {
                        float p0 = acc[mt][ntp][hlf * 2 + 0] + b0;
                        float p1 = acc[mt][ntp][hlf * 2 + 1] + b1;
                        float q0 = acc[mt][ntp + 1][hlf * 2 + 0] + b8;
                        float q1 = acc[mt][ntp + 1][hlf * 2 + 1] + b9;
                        if (doRelu) {
                            p0 = fmaxf(p0, 0.f); p1 = fmaxf(p1, 0.f);
                            q0 = fmaxf(q0, 0.f); q1 = fmaxf(q1, 0.f);
                        }
                        split_pair(p0, p1, v.x, v.z);
                        split_pair(q0, q1, v.y, v.w);
                    }
                    Cpack[dbase + (rloc ^ sx)] = v;
                }
            }
        }
    }
}

// --------------------------- GAT-specific kernels ---------------------------
__global__ void compute_al(const float* __restrict__ xp,
                           const float* __restrict__ asrc, const float* __restrict__ adst,
                           float* __restrict__ als, float* __restrict__ ald, int H) {
    int n = blockIdx.x, tid = threadIdx.x;
    int HC = H * CDIM;
    __shared__ float sh1[8], sh2[8];
    for (int h = 0; h < H; h++) {
        float v = xp[(size_t)n * HC + h * CDIM + tid];
        float s1 = v * asrc[h * CDIM + tid];
        float s2 = v * adst[h * CDIM + tid];
#pragma unroll
        for (int o = 16; o > 0; o >>= 1) {
            s1 += __shfl_down_sync(0xffffffffu, s1, o);
            s2 += __shfl_down_sync(0xffffffffu, s2, o);
        }
        if ((tid & 31) == 0) { sh1[tid >> 5] = s1; sh2[tid >> 5] = s2; }
        __syncthreads();
        if (tid < 8) {
            s1 = sh1[tid]; s2 = sh2[tid];
#pragma unroll
            for (int o = 4; o > 0; o >>= 1) {
                s1 += __shfl_down_sync(0xffu, s1, o);
                s2 += __shfl_down_sync(0xffu, s2, o);
            }
            if (tid == 0) { als[n * H + h] = s1; ald[n * H + h] = s2; }
        }
        __syncthreads();
    }
}

__global__ void edge_logits(const int* __restrict__ src, const int* __restrict__ dst,
                            const float* __restrict__ als, const float* __restrict__ ald,
                            float* __restrict__ elog, int E, int H) {
    int e = blockIdx.x * blockDim.x + threadIdx.x;
    if (e >= E) return;
    int s = src[e], d = dst[e];
    for (int h = 0; h < H; h++) {
        float v = als[s * H + h] + ald[d * H + h];
        elog[(size_t)e * H + h] = v > 0.f ? v : 0.2f * v;
    }
}

// aggregate writes packed panels (next GEMM's A operand)
__global__ void gat_aggregate(const float* __restrict__ xp, const float* __restrict__ elog,
                              const int* __restrict__ src, const int* __restrict__ sorted,
                              const int* __restrict__ off, const float* __restrict__ bias,
                              uint4* __restrict__ outP, int H) {
    int d = blockIdx.x, tid = threadIdx.x;
    int beg = off[d];
    int deg = off[d + 1] - beg;
    int HC = H * CDIM;
    __shared__ float sh[8];
    __shared__ float s_bcast;
    __shared__ float s_alpha[256];
    __shared__ int   s_row[256];
    __shared__ float s_out[512];

    if (deg <= 256) {
        if (tid < deg) s_row[tid] = src[sorted[beg + tid]];
        for (int h = 0; h < H; h++) {
            float mx = -1e30f;
            if (tid < deg) mx = elog[(size_t)sorted[beg + tid] * H + h];
#pragma unroll
            for (int o = 16; o > 0; o >>= 1)
                mx = fmaxf(mx, __shfl_down_sync(0xffffffffu, mx, o));
            if ((tid & 31) == 0) sh[tid >> 5] = mx;
            __syncthreads();
            if (tid < 8) {
                mx = sh[tid];
#pragma unroll
                for (int o = 4; o > 0; o >>= 1)
                    mx = fmaxf(mx, __shfl_down_sync(0xffu, mx, o));
                if (tid == 0) s_bcast = mx;
            }
            __syncthreads();
            float gmax = s_bcast;

            float ee = 0.f;
            if (tid < deg)
                ee = __expf(elog[(size_t)sorted[beg + tid] * H + h] - gmax);
            s_alpha[tid] = ee;
            float sm = ee;
#pragma unroll
            for (int o = 16; o > 0; o >>= 1) sm += __shfl_down_sync(0xffffffffu, sm, o);
            if ((tid & 31) == 0) sh[tid >> 5] = sm;
            __syncthreads();
            if (tid < 8) {
                sm = sh[tid];
#pragma unroll
                for (int o = 4; o > 0; o >>= 1) sm += __shfl_down_sync(0xffu, sm, o);
                if (tid == 0) s_bcast = sm;
            }
            __syncthreads();
            float inv = 1.f / (s_bcast + 1e-16f);

            const float* xph = xp + h * CDIM + tid;
            float a0 = 0.f, a1 = 0.f, a2 = 0.f, a3 = 0.f;
            int j = 0;
            for (; j + 4 <= deg; j += 4) {
                a0 += s_alpha[j + 0] * xph[(size_t)s_row[j + 0] * HC];
                a1 += s_alpha[j + 1] * xph[(size_t)s_row[j + 1] * HC];
                a2 += s_alpha[j + 2] * xph[(size_t)s_row[j + 2] * HC];
                a3 += s_alpha[j + 3] * xph[(size_t)s_row[j + 3] * HC];
            }
            for (; j < deg; j++)
                a0 += s_alpha[j] * xph[(size_t)s_row[j] * HC];
            s_out[h * CDIM + tid] =
                fmaxf(((a0 + a1) + (a2 + a3)) * inv + bias[h * CDIM + tid], 0.f);
            __syncthreads();
        }
    } else {
        for (int h = 0; h < H; h++) {
            float mx = -1e30f;
            for (int i = tid; i < deg; i += 256) {
                int e = sorted[beg + i];
                mx = fmaxf(mx, elog[(size_t)e * H + h]);
            }
#pragma unroll
            for (int o = 16; o > 0; o >>= 1)
                mx = fmaxf(mx, __shfl_down_sync(0xffffffffu, mx, o));
            if ((tid & 31) == 0) sh[tid >> 5] = mx;
            __syncthreads();
            if (tid < 8) {
                mx = sh[tid];
#pragma unroll
                for (int o = 4; o > 0; o >>= 1)
                    mx = fmaxf(mx, __shfl_down_sync(0xffu, mx, o));
                if (tid == 0) s_bcast = mx;
            }
            __syncthreads();
            float gmax = s_bcast;

            float sm = 0.f;
            for (int i = tid; i < deg; i += 256) {
                int e = sorted[beg + i];
                sm += __expf(elog[(size_t)e * H + h] - gmax);
            }
#pragma unroll
            for (int o = 16; o > 0; o >>= 1) sm += __shfl_down_sync(0xffffffffu, sm, o);
            if ((tid & 31) == 0) sh[tid >> 5] = sm;
            __syncthreads();
            if (tid < 8) {
                sm = sh[tid];
#pragma unroll
                for (int o = 4; o > 0; o >>= 1) sm += __shfl_down_sync(0xffu, sm, o);
                if (tid == 0) s_bcast = sm;
            }
            __syncthreads();
            float inv = 1.f / (s_bcast + 1e-16f);

            float acc = 0.f;
            for (int base = 0; base < deg; base += 256) {
                __syncthreads();
                int i = base + tid;
                if (i < deg) {
                    int e = sorted[beg + i];
                    s_alpha[tid] = __expf(elog[(size_t)e * H + h] - gmax) * inv;
                    s_row[tid]   = src[e];
                }
                __syncthreads();
                int lim = deg - base; if (lim > 256) lim = 256;
                for (int j = 0; j < lim; j++) {
                    acc += s_alpha[j] * xp[(size_t)s_row[j] * HC + h * CDIM + tid];
                }
            }
            s_out[h * CDIM + tid] = fmaxf(acc + bias[h * CDIM + tid], 0.f);
            __syncthreads();
        }
    }

    // pack the row into panels
    __syncthreads();
    int HC4 = HC >> 2;
    if (tid < HC4) {
        int c16 = tid >> 2, kq = tid & 3;
        int k0 = c16 * 16 + kq * 2;
        uint4 v;
        split_pair(s_out[k0], s_out[k0 + 1], v.x, v.z);
        split_pair(s_out[k0 + 8], s_out[k0 + 9], v.y, v.w);
        int t = d >> 7, dloc = d & 127;
        outP[((size_t)t * (HC >> 4) + c16) * 512 + kq * 128 + (dloc ^ (kq << 1))] = v;
    }
}

// --------------------------------- host -------------------------------------
static void run_gemm(cudaStream_t st, const uint4* Ap, const uint4* Bp,
                     const float* bias, float* C, uint4* Cpack, int KCpackTot,
                     int M, int N, int K, bool relu) {
    dim3 grid((N + 127) / 128, (M + 127) / 128);
    mma_gemm_kernel<<<grid, 256, GEMM_SMEM, st>>>(M, N, K, Ap, Bp, bias, C,
                                                  Cpack, KCpackTot, relu ? 1 : 0);
}

static void run_pack_w(cudaStream_t st, const float* W, int K, int N, uint4* out) {
    int total = ((N + 127) / 128) * (K >> 4) * 512;
    pack_w_kernel<<<(total + 255) / 256, 256, 0, st>>>(W, K, N, out, total);
}

struct Tower {
    float *bufA;
    uint4 *xsP, *aggBP, *aggCP, *m1P, *m2P, *finP;
    float *als, *ald, *elog;
    int *deg, *off, *cur, *sorted;
    uint4 *pW1, *pW2, *pL1, *pL2, *pL3;
};

static void run_tower(cudaStream_t st, const Tower& T,
                      const float* x, int N, int E, const int* src, const int* dst,
                      const float* W1, const float* a1s, const float* a1d, const float* b1,
                      const float* W2, const float* a2s, const float* a2d, const float* b2,
                      const float* lw1, const float* lb1, const float* lw2, const float* lb2,
                      const float* lw3, const float* lb3) {
    int NT = (N + 127) / 128;
    // launches 0..2, then GEMM1 at index 3 (ncu capture slot on X stream)
    int xTotal = NT * 16 * 512;
    pack_x_kernel<<<(xTotal + 255) / 256, 256, 0, st>>>(x, N, 256, T.xsP, xTotal);
    run_pack_w(st, W1, 256, 512, T.pW1);
    zero_int_kernel<<<(N + 256) / 256, 256, 0, st>>>(T.deg, N + 1);
    run_gemm(st, T.xsP, T.pW1, nullptr, T.bufA, nullptr, 0, N, 512, 256, false);

    zero_int_kernel<<<(N + 255) / 256, 256, 0, st>>>(T.cur, N);
    hist_kernel<<<(E + 255) / 256, 256, 0, st>>>(dst, E, T.deg);
    scan_kernel<<<1, 1024, 0, st>>>(T.deg, T.off, N);
    scatter_kernel<<<(E + 255) / 256, 256, 0, st>>>(dst, E, T.off, T.cur, T.sorted);

    compute_al<<<N, 256, 0, st>>>(T.bufA, a1s, a1d, T.als, T.ald, 2);
    edge_logits<<<(E + 255) / 256, 256, 0, st>>>(src, dst, T.als, T.ald, T.elog, E, 2);
    gat_aggregate<<<N, 256, 0, st>>>(T.bufA, T.elog, src, T.sorted, T.off, b1,
                                     T.aggBP, 2);

    run_pack_w(st, W2, 512, 256, T.pW2);
    run_gemm(st, T.aggBP, T.pW2, nullptr, T.bufA, nullptr, 0, N, 256, 512, false);
    compute_al<<<N, 256, 0, st>>>(T.bufA, a2s, a2d, T.als, T.ald, 1);
    edge_logits<<<(E + 255) / 256, 256, 0, st>>>(src, dst, T.als, T.ald, T.elog, E, 1);
    gat_aggregate<<<N, 256, 0, st>>>(T.bufA, T.elog, src, T.sorted, T.off, b2,
                                     T.aggCP, 1);

    run_pack_w(st, lw1, 256, 256, T.pL1);
    run_gemm(st, T.aggCP, T.pL1, lb1, nullptr, T.m1P, 16, N, 256, 256, true);
    run_pack_w(st, lw2, 256, 128, T.pL2);
    run_gemm(st, T.m1P, T.pL2, lb2, nullptr, T.m2P, 8, N, 128, 256, true);
    run_pack_w(st, lw3, 128, 64, T.pL3);
    run_gemm(st, T.m2P, T.pL3, lb3, nullptr, T.finP, 4, N, 64, 128, true);
}

#define GSA(p, s) cudaGetSymbolAddress((void**)&(p), s)

extern "C" void kernel_launch(void* const* d_in, const int* in_sizes, int n_in,
                              void* d_out, int out_size) {
    const float* x_m  = (const float*)d_in[0];
    const float* x_d  = (const float*)d_in[1];
    const int*   eix  = (const int*)d_in[2];
    const int*   eiy  = (const int*)d_in[3];
    const float* Wx1 = (const float*)d_in[4];
    const float* ax1s = (const float*)d_in[5];
    const float* ax1d = (const float*)d_in[6];
    const float* bx1 = (const float*)d_in[7];
    const float* Wx2 = (const float*)d_in[8];
    const float* ax2s = (const float*)d_in[9];
    const float* ax2d = (const float*)d_in[10];
    const float* bx2 = (const float*)d_in[11];
    const float* Wy1 = (const float*)d_in[12];
    const float* ay1s = (const float*)d_in[13];
    const float* ay1d = (const float*)d_in[14];
    const float* by1 = (const float*)d_in[15];
    const float* Wy2 = (const float*)d_in[16];
    const float* ay2s = (const float*)d_in[17];
    const float* ay2d = (const float*)d_in[18];
    const float* by2 = (const float*)d_in[19];
    const float* lwx1 = (const float*)d_in[20];
    const float* lbx1 = (const float*)d_in[21];
    const float* lwx2 = (const float*)d_in[22];
    const float* lbx2 = (const float*)d_in[23];
    const float* lwx3 = (const float*)d_in[24];
    const float* lbx3 = (const float*)d_in[25];
    const float* lwy1 = (const float*)d_in[26];
    const float* lby1 = (const float*)d_in[27];
    const float* lwy2 = (const float*)d_in[28];
    const float* lby2 = (const float*)d_in[29];
    const float* lwy3 = (const float*)d_in[30];
    const float* lby3 = (const float*)d_in[31];

    int M  = in_sizes[0] / 256;
    int D  = in_sizes[1] / 256;
    int EX = in_sizes[2] / 2;
    int EY = in_sizes[3] / 2;

    cudaFuncSetAttribute(mma_gemm_kernel,
                         cudaFuncAttributeMaxDynamicSharedMemorySize, GEMM_SMEM);

    Tower TX, TY;
    GSA(TX.bufA, g_bufA); GSA(TX.xsP, g_xsP); GSA(TX.aggBP, g_aggBP);
    GSA(TX.aggCP, g_aggCP); GSA(TX.m1P, g_m1P); GSA(TX.m2P, g_m2P);
    GSA(TX.finP, g_finP);
    GSA(TX.als, g_als); GSA(TX.ald, g_ald); GSA(TX.elog, g_elog);
    GSA(TX.deg, g_deg); GSA(TX.off, g_off); GSA(TX.cur, g_cur);
    GSA(TX.sorted, g_sorted);
    GSA(TX.pW1, g_pW1); GSA(TX.pW2, g_pW2);
    GSA(TX.pL1, g_pL1); GSA(TX.pL2, g_pL2); GSA(TX.pL3, g_pL3);

    GSA(TY.bufA, g2_bufA); GSA(TY.xsP, g2_xsP); GSA(TY.aggBP, g2_aggBP);
    GSA(TY.aggCP, g2_aggCP); GSA(TY.m1P, g2_m1P); GSA(TY.m2P, g2_m2P);
    GSA(TY.finP, g2_finP);
    GSA(TY.als, g2_als); GSA(TY.ald, g2_ald); GSA(TY.elog, g2_elog);
    GSA(TY.deg, g2_deg); GSA(TY.off, g2_off); GSA(TY.cur, g2_cur);
    GSA(TY.sorted, g2_sorted);
    GSA(TY.pW1, g2_pW1); GSA(TY.pW2, g2_pW2);
    GSA(TY.pL1, g2_pL1); GSA(TY.pL2, g2_pL2); GSA(TY.pL3, g2_pL3);

    cudaStream_t sY;
    cudaStreamCreateWithFlags(&sY, cudaStreamNonBlocking);
    cudaEvent_t evRoot, evY;
    cudaEventCreateWithFlags(&evRoot, cudaEventDisableTiming);
    cudaEventCreateWithFlags(&evY, cudaEventDisableTiming);

    cudaEventRecord(evRoot, 0);
    cudaStreamWaitEvent(sY, evRoot, 0);

    run_tower(0, TX, x_m, M, EX, eix, eix + EX,
              Wx1, ax1s, ax1d, bx1, Wx2, ax2s, ax2d, bx2,
              lwx1, lbx1, lwx2, lbx2, lwx3, lbx3);
    run_tower(sY, TY, x_d, D, EY, eiy, eiy + EY,
              Wy1, ay1s, ay1d, by1, Wy2, ay2s, ay2d, by2,
              lwy1, lby1, lwy2, lby2, lwy3, lby3);

    cudaEventRecord(evY, sY);
    cudaStreamWaitEvent(0, evY, 0);

    // final: A = X fin panels, B = Y fin panels (identical format), K = 64
    run_gemm(0, TX.finP, TY.finP, nullptr, (float*)d_out, nullptr, 0,
             M, D, 64, false);
}